// round 3
// baseline (speedup 1.0000x reference)
#include <cuda_runtime.h>

#define B 32
#define S 2048
#define H 32
#define HKV 8
#define G 4            // H / HKV
#define D 128
#define SPLITS 4
#define CHUNK (S / SPLITS)   // 512
#define TILE 64
#define NWARP 8
#define PADROW 132     // 128 + 4 pad floats: conflict-free LDS.128
#define SCALE 0.08838834764831845f
#define NEG -1e30f

// split-KV partial scratch (allocation-free: __device__ globals)
__device__ float g_part_o[B * HKV * SPLITS * G * D];
__device__ float g_part_m[B * HKV * SPLITS * G];
__device__ float g_part_l[B * HKV * SPLITS * G];

__global__ __launch_bounds__(256) void attn_split_kernel(
    const float* __restrict__ q,
    const float* __restrict__ knew,
    const float* __restrict__ vnew,
    const float* __restrict__ kbuf,
    const float* __restrict__ vbuf,
    const int*   __restrict__ req_to_token,
    const int*   __restrict__ seq_lens,
    const int*   __restrict__ out_cache_loc)
{
    const int bh    = blockIdx.x;           // b * HKV + kh
    const int b     = bh / HKV;
    const int kh    = bh % HKV;
    const int split = blockIdx.y;
    const int tid   = threadIdx.x;
    const int lane  = tid & 31;
    const int warp  = tid >> 5;

    const int seq_len = seq_lens[b];
    const int s0      = split * CHUNK;
    const int nt      = min(seq_len - s0, CHUNK);
    const int pbase   = (bh * SPLITS + split) * G;

    __shared__ float qs[G * PADROW];        // scaled q, padded (2.1 KB)
    __shared__ float sc[G][CHUNK];          // scores -> probs (8 KB)
    __shared__ float buf[TILE * PADROW];    // K stage tile, aliased as red[] (33.8 KB)
    __shared__ float ml_s[2][G];

    if (nt <= 0) {
        for (int i = tid; i < G * D; i += 256) g_part_o[(size_t)pbase * D + i] = 0.f;
        if (tid < G) { g_part_m[pbase + tid] = NEG; g_part_l[pbase + tid] = 0.f; }
        return;
    }

    const int out_loc = out_cache_loc[b];
    const float* knew_ptr = knew + ((size_t)b * HKV + kh) * D;
    const float* vnew_ptr = vnew + ((size_t)b * HKV + kh) * D;
    const int*   rtab     = req_to_token + (size_t)b * S + s0;

    // load q (scaled) into padded smem
    for (int i = tid; i < G * D; i += 256)
        qs[(i >> 7) * PADROW + (i & 127)] = q[((size_t)b * H + kh * G) * D + i] * SCALE;
    __syncthreads();

    // ---------- Pass 1: QK^T via smem staging (no shuffles) ----------
    const int tl_c = tid >> 2;      // 0..63 token-in-tile for compute
    const int g_c  = tid & 3;       // head for compute
    for (int t0 = 0; t0 < nt; t0 += TILE) {
        // stage: warp w loads tokens {w, w+8, ...} of this tile (coalesced float4)
        #pragma unroll
        for (int j = 0; j < TILE / NWARP; j++) {
            const int tl = j * NWARP + warp;
            const int t  = t0 + tl;
            if (t < nt) {
                const int loc = rtab[t];
                const float* kp = (loc == out_loc) ? knew_ptr
                                                   : (kbuf + ((size_t)loc * HKV + kh) * D);
                *(float4*)&buf[tl * PADROW + lane * 4] = *(const float4*)(kp + lane * 4);
            }
        }
        __syncthreads();
        // compute: thread = (token, head), full 128-dot from smem
        const int t = t0 + tl_c;
        if (t < nt) {
            const float* kr = &buf[tl_c * PADROW];
            const float* qr = &qs[g_c * PADROW];
            float acc = 0.f;
            #pragma unroll 8
            for (int i = 0; i < 32; i++) {
                float4 k4 = *(const float4*)(kr + 4 * i);
                float4 q4 = *(const float4*)(qr + 4 * i);
                acc += k4.x * q4.x + k4.y * q4.y + k4.z * q4.z + k4.w * q4.w;
            }
            sc[g_c][t] = acc;
        }
        __syncthreads();
    }

    // ---------- Pass 2: per-head max & sum-exp (warps 0..3, head = warp) ----------
    if (warp < G) {
        const int g = warp;
        float m = NEG;
        for (int t = lane; t < nt; t += 32) m = fmaxf(m, sc[g][t]);
        #pragma unroll
        for (int off = 16; off > 0; off >>= 1)
            m = fmaxf(m, __shfl_xor_sync(0xffffffffu, m, off));
        float l = 0.f;
        for (int t = lane; t < nt; t += 32) {
            float e = __expf(sc[g][t] - m);
            sc[g][t] = e;
            l += e;
        }
        #pragma unroll
        for (int off = 16; off > 0; off >>= 1)
            l += __shfl_xor_sync(0xffffffffu, l, off);
        if (lane == 0) { ml_s[0][g] = m; ml_s[1][g] = l; }
    }
    __syncthreads();

    // ---------- Pass 3: P @ V (warp-per-token, register accumulate) ----------
    float4 acc[G];
    #pragma unroll
    for (int g = 0; g < G; g++) acc[g] = make_float4(0.f, 0.f, 0.f, 0.f);

    for (int t = warp; t < nt; t += NWARP) {
        const int loc = rtab[t];
        const float* vp = (loc == out_loc) ? vnew_ptr
                                           : (vbuf + ((size_t)loc * HKV + kh) * D);
        float4 v4 = *(const float4*)(vp + lane * 4);
        #pragma unroll
        for (int g = 0; g < G; g++) {
            const float p = sc[g][t];      // smem broadcast
            acc[g].x += p * v4.x; acc[g].y += p * v4.y;
            acc[g].z += p * v4.z; acc[g].w += p * v4.w;
        }
    }
    // deterministic cross-warp reduction via smem (red aliases buf; disjoint in time)
    float* red = buf;                       // red[NWARP][G*D] = 16 KB <= 33.8 KB
    #pragma unroll
    for (int g = 0; g < G; g++)
        *(float4*)&red[(warp * G + g) * D + lane * 4] = acc[g];
    __syncthreads();

    for (int i = tid; i < G * D; i += 256) {
        float s = red[i];
        #pragma unroll
        for (int w = 1; w < NWARP; w++) s += red[w * G * D + i];
        g_part_o[(size_t)pbase * D + i] = s;
    }
    if (tid < G) {
        g_part_m[pbase + tid] = ml_s[0][tid];
        g_part_l[pbase + tid] = ml_s[1][tid];
    }
}

// merge SPLITS partials per (b, kh): one thread per (g, d)
__global__ __launch_bounds__(512) void reduce_kernel(float* __restrict__ out)
{
    const int bh  = blockIdx.x;             // b * HKV + kh
    const int b   = bh / HKV;
    const int kh  = bh % HKV;
    const int tid = threadIdx.x;
    const int g   = tid >> 7;
    const int d   = tid & 127;

    float m = NEG;
    #pragma unroll
    for (int sp = 0; sp < SPLITS; sp++)
        m = fmaxf(m, g_part_m[(bh * SPLITS + sp) * G + g]);

    float L = 0.f, o = 0.f;
    #pragma unroll
    for (int sp = 0; sp < SPLITS; sp++) {
        const int   pi = (bh * SPLITS + sp) * G + g;
        const float w  = __expf(g_part_m[pi] - m);
        L += g_part_l[pi] * w;
        o += g_part_o[(size_t)pi * D + d] * w;
    }
    out[((size_t)b * H + kh * G + g) * D + d] = o / L;
}

extern "C" void kernel_launch(void* const* d_in, const int* in_sizes, int n_in,
                              void* d_out, int out_size)
{
    const float* q        = (const float*)d_in[0];
    const float* knew     = (const float*)d_in[1];
    const float* vnew     = (const float*)d_in[2];
    const float* kbuf     = (const float*)d_in[3];
    const float* vbuf     = (const float*)d_in[4];
    const int*   req2tok  = (const int*)d_in[5];
    const int*   seq_lens = (const int*)d_in[6];
    const int*   out_loc  = (const int*)d_in[7];
    float*       out      = (float*)d_out;

    dim3 grid(B * HKV, SPLITS);
    attn_split_kernel<<<grid, 256>>>(q, knew, vnew, kbuf, vbuf,
                                     req2tok, seq_lens, out_loc);
    reduce_kernel<<<B * HKV, 512>>>(out);
}